// round 4
// baseline (speedup 1.0000x reference)
#include <cuda_runtime.h>
#include <math.h>

#define BB 16
#define SS 8192
#define DD 512
#define SCALE_F 0.125

// ---------------- scratch (__device__ globals; no allocations allowed) --------
__device__ double        g_hs[BB * DD];        // sum of normalized tokens per batch (fp64)
__device__ float         g_v[BB * DD];         // v[b] = Wq^T (Wk hs[b])
__device__ float         g_invnorm[BB * SS];   // 1/max(||hidden_row||, 1e-12)
__device__ unsigned char g_hard[BB * SS];      // boundary bits
__device__ int           g_keptidx[BB * SS];   // compacted kept indices per batch
__device__ int           g_count[BB];          // kept counts

__device__ __forceinline__ void pf_l2(const void* p) {
    asm volatile("prefetch.global.L2 [%0];" :: "l"(p));
}

// ---------------- kernel 0: zero hs ------------------------------------------
__global__ void zero_hs_kernel() {
    int i = blockIdx.x * blockDim.x + threadIdx.x;
    if (i < BB * DD) g_hs[i] = 0.0;
}

// ---------------- kernel 1: per-token norm + hs accumulation -----------------
// grid = 1024 blocks (64 per batch), 256 threads (8 warps), warp = 16 tokens
// (4 iterations of 4 tokens). L2 prefetch for the next iteration's 8KB.
__global__ void __launch_bounds__(256, 4) norm_hs_kernel(const float* __restrict__ hidden) {
    __shared__ float sh_warp[8 * DD];   // per-warp partial hs (16 KB)
    int warp = threadIdx.x >> 5;
    int lane = threadIdx.x & 31;
    int batch = blockIdx.x >> 6;                       // 64 blocks per batch
    int tok0  = ((blockIdx.x & 63) * 8 + warp) * 16;   // 16 tokens per warp

    float accf[16];
#pragma unroll
    for (int k = 0; k < 16; k++) accf[k] = 0.0f;

    const float* hbase = hidden + (size_t)batch * SS * DD;
    const float4* base = (const float4*)hbase;
    // prefetch line offsets for the two lines this lane covers per 4-token group
    int pr = lane >> 4, pc = (lane & 15) * 32;          // row-in-group(0..1), col
#pragma unroll
    for (int t = 0; t < 16; t += 4) {
        // ---- prefetch next 4 tokens (64 lines, 2 prefetches per lane) ----
        if (t + 4 < 16) {
            const float* nb = hbase + (size_t)(tok0 + t + 4) * DD;
            pf_l2(nb + (size_t)pr * DD + pc);
            pf_l2(nb + (size_t)(pr + 2) * DD + pc);
        }
        // ---- batched loads: 4 tokens x 4 float4 each ----
        float4 x[4][4];
#pragma unroll
        for (int i = 0; i < 4; i++) {
            const float4* row = base + (size_t)(tok0 + t + i) * (DD / 4);
#pragma unroll
            for (int k = 0; k < 4; k++) x[i][k] = row[lane + 32 * k];
        }
        // ---- per-lane sum of squares: fp32, 4 independent chains/token ----
        float ss[4];
#pragma unroll
        for (int i = 0; i < 4; i++) {
            float s0 = 0.f, s1 = 0.f, s2 = 0.f, s3 = 0.f;
#pragma unroll
            for (int k = 0; k < 4; k++) {
                s0 = fmaf(x[i][k].x, x[i][k].x, s0);
                s1 = fmaf(x[i][k].y, x[i][k].y, s1);
                s2 = fmaf(x[i][k].z, x[i][k].z, s2);
                s3 = fmaf(x[i][k].w, x[i][k].w, s3);
            }
            ss[i] = (s0 + s1) + (s2 + s3);
        }
        // ---- interleaved fp32 butterflies ----
#pragma unroll
        for (int o = 16; o > 0; o >>= 1) {
#pragma unroll
            for (int i = 0; i < 4; i++)
                ss[i] += __shfl_xor_sync(0xffffffffu, ss[i], o);
        }
        float invf[4];
#pragma unroll
        for (int i = 0; i < 4; i++)
            invf[i] = 1.0f / fmaxf(sqrtf(ss[i]), 1e-12f);

        if (lane < 4) {
            float iv = invf[0];
            if (lane == 1) iv = invf[1];
            else if (lane == 2) iv = invf[2];
            else if (lane == 3) iv = invf[3];
            g_invnorm[batch * SS + tok0 + t + lane] = iv;
        }
        // ---- hs accumulation: 16 independent fp32 chains ----
#pragma unroll
        for (int i = 0; i < 4; i++) {
#pragma unroll
            for (int k = 0; k < 4; k++) {
                accf[4 * k + 0] = fmaf(x[i][k].x, invf[i], accf[4 * k + 0]);
                accf[4 * k + 1] = fmaf(x[i][k].y, invf[i], accf[4 * k + 1]);
                accf[4 * k + 2] = fmaf(x[i][k].z, invf[i], accf[4 * k + 2]);
                accf[4 * k + 3] = fmaf(x[i][k].w, invf[i], accf[4 * k + 3]);
            }
        }
    }
    // ---- per-warp partials -> shared (no atomics) ----
    float* my = sh_warp + warp * DD;
#pragma unroll
    for (int k = 0; k < 4; k++) {
        int c = 4 * (lane + 32 * k);
        my[c + 0] = accf[4 * k + 0];
        my[c + 1] = accf[4 * k + 1];
        my[c + 2] = accf[4 * k + 2];
        my[c + 3] = accf[4 * k + 3];
    }
    __syncthreads();
    // ---- block combine in fp64, one global fp64 atomic per column ----
    for (int c = threadIdx.x; c < DD; c += blockDim.x) {
        double s = 0.0;
#pragma unroll
        for (int w = 0; w < 8; w++) s += (double)sh_warp[w * DD + c];
        atomicAdd(&g_hs[batch * DD + c], s);
    }
}

// ---------------- kernel 2: v[b] = Wq^T (Wk hs[b])  (fp64, tiny) -------------
__global__ void matvec_kernel(const float* __restrict__ Wq, const float* __restrict__ Wk) {
    __shared__ double sh_hs[DD];
    __shared__ double sh_t[DD];
    int b = blockIdx.x;
    int tid = threadIdx.x;
    sh_hs[tid] = g_hs[b * DD + tid];
    __syncthreads();

    int warp = tid >> 5, lane = tid & 31;  // 16 warps
    for (int d = warp; d < DD; d += 16) {
        const float* wrow = Wk + (size_t)d * DD;
        double s = 0.0;
        for (int e = lane; e < DD; e += 32) s += (double)wrow[e] * sh_hs[e];
#pragma unroll
        for (int o = 16; o > 0; o >>= 1) s += __shfl_down_sync(0xffffffffu, s, o);
        if (lane == 0) sh_t[d] = s;
    }
    __syncthreads();

    double acc = 0.0;
    for (int d = 0; d < DD; d++) acc += (double)Wq[(size_t)d * DD + tid] * sh_t[d];
    g_v[b * DD + tid] = (float)acc;
}

// ---------------- kernel 3: scores + hard bits --------------------------------
// grid = 1024 blocks, warp = 16 tokens, L2 prefetch one iteration ahead.
// fp32 per-lane partials, fp64 butterfly (protects threshold sign decisions).
__global__ void __launch_bounds__(256, 4) scores_kernel(const float* __restrict__ hidden,
                                                        const float* __restrict__ noise) {
    __shared__ float sh_v[DD];
    int warp = threadIdx.x >> 5;
    int lane = threadIdx.x & 31;
    int batch = blockIdx.x >> 6;
    int tok0  = ((blockIdx.x & 63) * 8 + warp) * 16;

    for (int i = threadIdx.x; i < DD; i += blockDim.x) sh_v[i] = g_v[batch * DD + i];
    __syncthreads();

    const float4* vv = (const float4*)sh_v;
    float4 w[4];
#pragma unroll
    for (int k = 0; k < 4; k++) w[k] = vv[lane + 32 * k];

    const float* hbase = hidden + (size_t)batch * SS * DD;
    const float4* base = (const float4*)hbase;
    int pr = lane >> 4, pc = (lane & 15) * 32;
#pragma unroll
    for (int t = 0; t < 16; t += 4) {
        if (t + 4 < 16) {
            const float* nb = hbase + (size_t)(tok0 + t + 4) * DD;
            pf_l2(nb + (size_t)pr * DD + pc);
            pf_l2(nb + (size_t)(pr + 2) * DD + pc);
        }
        float4 x[4][4];
#pragma unroll
        for (int i = 0; i < 4; i++) {
            const float4* row = base + (size_t)(tok0 + t + i) * (DD / 4);
#pragma unroll
            for (int k = 0; k < 4; k++) x[i][k] = row[lane + 32 * k];
        }
        double dot[4];
#pragma unroll
        for (int i = 0; i < 4; i++) {
            float s0 = 0.f, s1 = 0.f, s2 = 0.f, s3 = 0.f;
#pragma unroll
            for (int k = 0; k < 4; k++) {
                s0 = fmaf(x[i][k].x, w[k].x, s0);
                s1 = fmaf(x[i][k].y, w[k].y, s1);
                s2 = fmaf(x[i][k].z, w[k].z, s2);
                s3 = fmaf(x[i][k].w, w[k].w, s3);
            }
            dot[i] = ((double)s0 + (double)s1) + ((double)s2 + (double)s3);
        }
#pragma unroll
        for (int o = 16; o > 0; o >>= 1) {
#pragma unroll
            for (int i = 0; i < 4; i++)
                dot[i] += __shfl_xor_sync(0xffffffffu, dot[i], o);
        }
        if (lane < 4) {
            double d = dot[0];
            if (lane == 1) d = dot[1];
            else if (lane == 2) d = dot[2];
            else if (lane == 3) d = dot[3];
            int g = batch * SS + tok0 + t + lane;
            double score = SCALE_F * (double)g_invnorm[g] * d;
            float nz = noise[g];
            double logistic = (double)logf(nz) - (double)log1pf(-nz);
            g_hard[g] = (score + logistic > 0.0) ? 1 : 0;
        }
    }
}

// ---------------- kernel 4: per-batch stable compaction scan ------------------
__global__ void scan_kernel() {
    int b = blockIdx.x;
    int tid = threadIdx.x;
    const int TPT = SS / 1024;  // 8
    int base = b * SS + tid * TPT;

    int loc[TPT];
    int cnt = 0;
#pragma unroll
    for (int i = 0; i < TPT; i++) { loc[i] = g_hard[base + i]; cnt += loc[i]; }

    int lane = tid & 31, warp = tid >> 5;
    int v = cnt;
#pragma unroll
    for (int o = 1; o < 32; o <<= 1) {
        int n = __shfl_up_sync(0xffffffffu, v, o);
        if (lane >= o) v += n;
    }
    __shared__ int wsum[32];
    if (lane == 31) wsum[warp] = v;
    __syncthreads();
    if (warp == 0) {
        int w = wsum[lane];
#pragma unroll
        for (int o = 1; o < 32; o <<= 1) {
            int n = __shfl_up_sync(0xffffffffu, w, o);
            if (lane >= o) w += n;
        }
        wsum[lane] = w;
    }
    __syncthreads();
    int excl = (v - cnt) + (warp > 0 ? wsum[warp - 1] : 0);

    int pos = excl;
#pragma unroll
    for (int i = 0; i < TPT; i++)
        if (loc[i]) g_keptidx[b * SS + (pos++)] = tid * TPT + i;
    if (tid == 1023) g_count[b] = excl + cnt;
}

// ---------------- kernel 5: write pooled (gather kept rows, zero the rest) ----
// 2 output rows per warp (MLP 8) + sorted-gather L2 prefetch 64 rows ahead.
__global__ void __launch_bounds__(256, 8) writeout_kernel(const float* __restrict__ hidden,
                                                          float* __restrict__ out) {
    int wg = blockIdx.x * (blockDim.x >> 5) + (threadIdx.x >> 5);
    int lane = threadIdx.x & 31;
    int b = wg >> 12;          // 4096 warps per batch (2 rows each)
    int i0 = (wg & 4095) * 2;
    int cnt = g_count[b];

    // prefetch the source row for output row i0+64 (indices are sorted)
    if (i0 + 64 < cnt) {
        int sp = g_keptidx[b * SS + i0 + 64];
        pf_l2(hidden + ((size_t)b * SS + sp) * DD + lane * 16);
    }

    bool v0 = i0 < cnt, v1 = (i0 + 1) < cnt;
    int s0 = v0 ? g_keptidx[b * SS + i0] : 0;
    int s1 = v1 ? g_keptidx[b * SS + i0 + 1] : 0;
    float inv0 = v0 ? g_invnorm[b * SS + s0] : 0.f;
    float inv1 = v1 ? g_invnorm[b * SS + s1] : 0.f;

    const float4* r0 = (const float4*)hidden + ((size_t)b * SS + s0) * (DD / 4);
    const float4* r1 = (const float4*)hidden + ((size_t)b * SS + s1) * (DD / 4);
    float4 a[4], c[4];
    float4 z = make_float4(0.f, 0.f, 0.f, 0.f);
#pragma unroll
    for (int k = 0; k < 4; k++) a[k] = v0 ? r0[lane + 32 * k] : z;
#pragma unroll
    for (int k = 0; k < 4; k++) c[k] = v1 ? r1[lane + 32 * k] : z;

    float4* o0 = (float4*)out + ((size_t)b * SS + i0) * (DD / 4);
    float4* o1 = o0 + (DD / 4);
#pragma unroll
    for (int k = 0; k < 4; k++) {
        float4 x = a[k];
        x.x *= inv0; x.y *= inv0; x.z *= inv0; x.w *= inv0;
        o0[lane + 32 * k] = x;
    }
#pragma unroll
    for (int k = 0; k < 4; k++) {
        float4 x = c[k];
        x.x *= inv1; x.y *= inv1; x.z *= inv1; x.w *= inv1;
        o1[lane + 32 * k] = x;
    }
}

// ---------------- kernel 6: binomial loss -> tail of output -------------------
__global__ void loss_kernel(float* __restrict__ out, long long out_size) {
    __shared__ double sh[BB];
    __shared__ float sh_loss;
    int tid = threadIdx.x;
    if (tid < BB) {
        double k = (double)g_count[tid];
        double n = (double)SS;
        double lp = lgamma(n + 1.0) - lgamma(k + 1.0) - lgamma(n - k + 1.0)
                  + k * log(0.2) + (n - k) * log1p(-0.2);
        sh[tid] = lp;
    }
    __syncthreads();
    if (tid == 0) {
        double m = 0.0;
        for (int b = 0; b < BB; b++) m += sh[b];
        m /= (double)BB;
        sh_loss = (float)(-m / (double)SS);
    }
    __syncthreads();
    long long start = (long long)BB * SS * DD;
    for (long long i = start + tid; i < out_size; i += blockDim.x) out[i] = sh_loss;
}

// ---------------- launch ------------------------------------------------------
extern "C" void kernel_launch(void* const* d_in, const int* in_sizes, int n_in,
                              void* d_out, int out_size) {
    const float* hidden = (const float*)d_in[0];
    const float* Wq     = (const float*)d_in[1];
    const float* Wk     = (const float*)d_in[2];
    const float* noise  = (const float*)d_in[3];
    float* out = (float*)d_out;

    zero_hs_kernel<<<(BB * DD + 511) / 512, 512>>>();
    norm_hs_kernel<<<1024, 256>>>(hidden);
    matvec_kernel<<<BB, DD>>>(Wq, Wk);
    scores_kernel<<<1024, 256>>>(hidden, noise);
    scan_kernel<<<BB, 1024>>>();
    writeout_kernel<<<(BB * SS) / 16, 256>>>(hidden, out);
    loss_kernel<<<1, 256>>>(out, (long long)out_size);
}

// round 5
// speedup vs baseline: 1.1017x; 1.1017x over previous
#include <cuda_runtime.h>
#include <math.h>

#define BB 16
#define SS 8192
#define DD 512
#define SCALE_F 0.125
#define PAD 33   // smem row pad (floats): bank = row + j -> conflict-free scalar reads

// ---------------- scratch (__device__ globals; no allocations allowed) --------
__device__ double        g_hs[BB * DD];        // sum of normalized tokens per batch (fp64)
__device__ float         g_v[BB * DD];         // v[b] = Wq^T (Wk hs[b])
__device__ float         g_invnorm[BB * SS];   // 1/max(||hidden_row||, 1e-12)
__device__ unsigned char g_hard[BB * SS];      // boundary bits
__device__ int           g_keptidx[BB * SS];   // compacted kept indices per batch
__device__ int           g_count[BB];          // kept counts

// ---------------- kernel 0: zero hs ------------------------------------------
__global__ void zero_hs_kernel() {
    int i = blockIdx.x * blockDim.x + threadIdx.x;
    if (i < BB * DD) g_hs[i] = 0.0;
}

// ---------------- kernel 1: invnorm (pure stream + warp-local smem reduce) ----
// grid = 1024 (64 per batch), 256 thr (8 warps), warp = 16 tokens, 2 tokens/iter.
// Phase A: per-lane fp32 sumsq partials -> smem (no cross-lane deps at all).
// Phase B: lanes 0-15 reduce one token each (fp32 pairwise tree), write invnorm.
__global__ void __launch_bounds__(256, 4) invnorm_kernel(const float* __restrict__ hidden) {
    __shared__ float part[128 * PAD];
    int warp = threadIdx.x >> 5;
    int lane = threadIdx.x & 31;
    int batch = blockIdx.x >> 6;
    int tok0  = ((blockIdx.x & 63) * 8 + warp) * 16;

    const float4* base = (const float4*)(hidden + (size_t)batch * SS * DD);
#pragma unroll
    for (int t = 0; t < 16; t += 2) {
#pragma unroll
        for (int i = 0; i < 2; i++) {
            const float4* row = base + (size_t)(tok0 + t + i) * (DD / 4);
            float4 x0 = row[lane];
            float4 x1 = row[lane + 32];
            float4 x2 = row[lane + 64];
            float4 x3 = row[lane + 96];
            float s0 = 0.f, s1 = 0.f, s2 = 0.f, s3 = 0.f;
            s0 = fmaf(x0.x, x0.x, s0); s1 = fmaf(x0.y, x0.y, s1);
            s2 = fmaf(x0.z, x0.z, s2); s3 = fmaf(x0.w, x0.w, s3);
            s0 = fmaf(x1.x, x1.x, s0); s1 = fmaf(x1.y, x1.y, s1);
            s2 = fmaf(x1.z, x1.z, s2); s3 = fmaf(x1.w, x1.w, s3);
            s0 = fmaf(x2.x, x2.x, s0); s1 = fmaf(x2.y, x2.y, s1);
            s2 = fmaf(x2.z, x2.z, s2); s3 = fmaf(x2.w, x2.w, s3);
            s0 = fmaf(x3.x, x3.x, s0); s1 = fmaf(x3.y, x3.y, s1);
            s2 = fmaf(x3.z, x3.z, s2); s3 = fmaf(x3.w, x3.w, s3);
            part[(warp * 16 + t + i) * PAD + lane] = (s0 + s1) + (s2 + s3);
        }
    }
    __syncwarp();
    if (lane < 16) {
        int r = warp * 16 + lane;
        const float* p = &part[r * PAD];
        float q[32];
#pragma unroll
        for (int j = 0; j < 32; j++) q[j] = p[j];
        // fp32 pairwise tree
#pragma unroll
        for (int w = 16; w > 0; w >>= 1)
#pragma unroll
            for (int j = 0; j < 32; j++) if (j < w) q[j] = q[j] + q[j + w];
        g_invnorm[batch * SS + tok0 + lane] = 1.0f / fmaxf(sqrtf(q[0]), 1e-12f);
    }
}

// ---------------- kernel 2: hs accumulation (pure stream) ---------------------
// grid = 1024, warp = 16 tokens, 2 tokens/iter. 16 independent fp32 chains per
// lane; fp64 only in the block combine + global atomic.
__global__ void __launch_bounds__(256, 4) hs_kernel(const float* __restrict__ hidden) {
    __shared__ float sh_warp[8 * DD];
    int warp = threadIdx.x >> 5;
    int lane = threadIdx.x & 31;
    int batch = blockIdx.x >> 6;
    int tok0  = ((blockIdx.x & 63) * 8 + warp) * 16;

    float accf[16];
#pragma unroll
    for (int k = 0; k < 16; k++) accf[k] = 0.0f;

    const float4* base = (const float4*)(hidden + (size_t)batch * SS * DD);
    const float* invp = g_invnorm + batch * SS + tok0;
#pragma unroll
    for (int t = 0; t < 16; t += 2) {
        float inv0 = invp[t];
        float inv1 = invp[t + 1];
        float4 x[2][4];
#pragma unroll
        for (int i = 0; i < 2; i++) {
            const float4* row = base + (size_t)(tok0 + t + i) * (DD / 4);
#pragma unroll
            for (int k = 0; k < 4; k++) x[i][k] = row[lane + 32 * k];
        }
#pragma unroll
        for (int k = 0; k < 4; k++) {
            accf[4 * k + 0] = fmaf(x[0][k].x, inv0, accf[4 * k + 0]);
            accf[4 * k + 1] = fmaf(x[0][k].y, inv0, accf[4 * k + 1]);
            accf[4 * k + 2] = fmaf(x[0][k].z, inv0, accf[4 * k + 2]);
            accf[4 * k + 3] = fmaf(x[0][k].w, inv0, accf[4 * k + 3]);
            accf[4 * k + 0] = fmaf(x[1][k].x, inv1, accf[4 * k + 0]);
            accf[4 * k + 1] = fmaf(x[1][k].y, inv1, accf[4 * k + 1]);
            accf[4 * k + 2] = fmaf(x[1][k].z, inv1, accf[4 * k + 2]);
            accf[4 * k + 3] = fmaf(x[1][k].w, inv1, accf[4 * k + 3]);
        }
    }
    float* my = sh_warp + warp * DD;
#pragma unroll
    for (int k = 0; k < 4; k++) {
        int c = 4 * (lane + 32 * k);
        my[c + 0] = accf[4 * k + 0];
        my[c + 1] = accf[4 * k + 1];
        my[c + 2] = accf[4 * k + 2];
        my[c + 3] = accf[4 * k + 3];
    }
    __syncthreads();
    for (int c = threadIdx.x; c < DD; c += blockDim.x) {
        double s = 0.0;
#pragma unroll
        for (int w = 0; w < 8; w++) s += (double)sh_warp[w * DD + c];
        atomicAdd(&g_hs[batch * DD + c], s);
    }
}

// ---------------- kernel 3: v[b] = Wq^T (Wk hs[b])  (fp64, tiny) -------------
__global__ void matvec_kernel(const float* __restrict__ Wq, const float* __restrict__ Wk) {
    __shared__ double sh_hs[DD];
    __shared__ double sh_t[DD];
    int b = blockIdx.x;
    int tid = threadIdx.x;
    sh_hs[tid] = g_hs[b * DD + tid];
    __syncthreads();

    int warp = tid >> 5, lane = tid & 31;  // 16 warps
    for (int d = warp; d < DD; d += 16) {
        const float* wrow = Wk + (size_t)d * DD;
        double s = 0.0;
        for (int e = lane; e < DD; e += 32) s += (double)wrow[e] * sh_hs[e];
#pragma unroll
        for (int o = 16; o > 0; o >>= 1) s += __shfl_down_sync(0xffffffffu, s, o);
        if (lane == 0) sh_t[d] = s;
    }
    __syncthreads();

    double acc = 0.0;
    for (int d = 0; d < DD; d++) acc += (double)Wq[(size_t)d * DD + tid] * sh_t[d];
    g_v[b * DD + tid] = (float)acc;
}

// ---------------- kernel 4: scores + hard bits (stream + warp-local reduce) ---
// Phase A: per-lane fp32 dot partials -> smem (no cross-lane deps).
// Phase B: lanes 0-15 reduce one token each with an fp64 pairwise tree
// (protects the threshold sign decisions), then threshold + write bit.
__global__ void __launch_bounds__(256, 4) scores_kernel(const float* __restrict__ hidden,
                                                        const float* __restrict__ noise) {
    __shared__ float part[128 * PAD];
    __shared__ float sh_v[DD];
    int warp = threadIdx.x >> 5;
    int lane = threadIdx.x & 31;
    int batch = blockIdx.x >> 6;
    int tok0  = ((blockIdx.x & 63) * 8 + warp) * 16;

    for (int i = threadIdx.x; i < DD; i += blockDim.x) sh_v[i] = g_v[batch * DD + i];
    __syncthreads();

    const float4* vv = (const float4*)sh_v;
    float4 w0 = vv[lane], w1 = vv[lane + 32], w2 = vv[lane + 64], w3 = vv[lane + 96];

    const float4* base = (const float4*)(hidden + (size_t)batch * SS * DD);
#pragma unroll
    for (int t = 0; t < 16; t += 2) {
#pragma unroll
        for (int i = 0; i < 2; i++) {
            const float4* row = base + (size_t)(tok0 + t + i) * (DD / 4);
            float4 x0 = row[lane];
            float4 x1 = row[lane + 32];
            float4 x2 = row[lane + 64];
            float4 x3 = row[lane + 96];
            float s0 = 0.f, s1 = 0.f, s2 = 0.f, s3 = 0.f;
            s0 = fmaf(x0.x, w0.x, s0); s1 = fmaf(x0.y, w0.y, s1);
            s2 = fmaf(x0.z, w0.z, s2); s3 = fmaf(x0.w, w0.w, s3);
            s0 = fmaf(x1.x, w1.x, s0); s1 = fmaf(x1.y, w1.y, s1);
            s2 = fmaf(x1.z, w1.z, s2); s3 = fmaf(x1.w, w1.w, s3);
            s0 = fmaf(x2.x, w2.x, s0); s1 = fmaf(x2.y, w2.y, s1);
            s2 = fmaf(x2.z, w2.z, s2); s3 = fmaf(x2.w, w2.w, s3);
            s0 = fmaf(x3.x, w3.x, s0); s1 = fmaf(x3.y, w3.y, s1);
            s2 = fmaf(x3.z, w3.z, s2); s3 = fmaf(x3.w, w3.w, s3);
            part[(warp * 16 + t + i) * PAD + lane] = (s0 + s1) + (s2 + s3);
        }
    }
    __syncwarp();
    if (lane < 16) {
        int r = warp * 16 + lane;
        const float* p = &part[r * PAD];
        // fp64 pairwise tree over the 32 fp32 partials
        double q[16];
#pragma unroll
        for (int j = 0; j < 16; j++) q[j] = (double)p[j] + (double)p[j + 16];
#pragma unroll
        for (int w = 8; w > 0; w >>= 1)
#pragma unroll
            for (int j = 0; j < 16; j++) if (j < w) q[j] = q[j] + q[j + w];
        int g = batch * SS + tok0 + lane;
        double score = SCALE_F * (double)g_invnorm[g] * q[0];
        float nz = noise[g];
        double logistic = (double)logf(nz) - (double)log1pf(-nz);
        g_hard[g] = (score + logistic > 0.0) ? 1 : 0;
    }
}

// ---------------- kernel 5: per-batch stable compaction scan ------------------
__global__ void scan_kernel() {
    int b = blockIdx.x;
    int tid = threadIdx.x;
    const int TPT = SS / 1024;  // 8
    int base = b * SS + tid * TPT;

    int loc[TPT];
    int cnt = 0;
#pragma unroll
    for (int i = 0; i < TPT; i++) { loc[i] = g_hard[base + i]; cnt += loc[i]; }

    int lane = tid & 31, warp = tid >> 5;
    int v = cnt;
#pragma unroll
    for (int o = 1; o < 32; o <<= 1) {
        int n = __shfl_up_sync(0xffffffffu, v, o);
        if (lane >= o) v += n;
    }
    __shared__ int wsum[32];
    if (lane == 31) wsum[warp] = v;
    __syncthreads();
    if (warp == 0) {
        int w = wsum[lane];
#pragma unroll
        for (int o = 1; o < 32; o <<= 1) {
            int n = __shfl_up_sync(0xffffffffu, w, o);
            if (lane >= o) w += n;
        }
        wsum[lane] = w;
    }
    __syncthreads();
    int excl = (v - cnt) + (warp > 0 ? wsum[warp - 1] : 0);

    int pos = excl;
#pragma unroll
    for (int i = 0; i < TPT; i++)
        if (loc[i]) g_keptidx[b * SS + (pos++)] = tid * TPT + i;
    if (tid == 1023) g_count[b] = excl + cnt;
}

// ---------------- kernel 6: write pooled (gather kept rows, zero the rest) ----
// 2 output rows per warp (8 loads in flight), launch_bounds 4 (no spills).
__global__ void __launch_bounds__(256, 4) writeout_kernel(const float* __restrict__ hidden,
                                                          float* __restrict__ out) {
    int wg = blockIdx.x * (blockDim.x >> 5) + (threadIdx.x >> 5);
    int lane = threadIdx.x & 31;
    int b = wg >> 12;          // 4096 warps per batch (2 rows each)
    int i0 = (wg & 4095) * 2;
    int cnt = g_count[b];

    bool v0 = i0 < cnt, v1 = (i0 + 1) < cnt;
    int s0 = v0 ? g_keptidx[b * SS + i0] : 0;
    int s1 = v1 ? g_keptidx[b * SS + i0 + 1] : 0;
    float inv0 = v0 ? g_invnorm[b * SS + s0] : 0.f;
    float inv1 = v1 ? g_invnorm[b * SS + s1] : 0.f;

    const float4* r0 = (const float4*)hidden + ((size_t)b * SS + s0) * (DD / 4);
    const float4* r1 = (const float4*)hidden + ((size_t)b * SS + s1) * (DD / 4);
    float4 a[4], c[4];
    float4 z = make_float4(0.f, 0.f, 0.f, 0.f);
#pragma unroll
    for (int k = 0; k < 4; k++) a[k] = v0 ? r0[lane + 32 * k] : z;
#pragma unroll
    for (int k = 0; k < 4; k++) c[k] = v1 ? r1[lane + 32 * k] : z;

    float4* o0 = (float4*)out + ((size_t)b * SS + i0) * (DD / 4);
    float4* o1 = o0 + (DD / 4);
#pragma unroll
    for (int k = 0; k < 4; k++) {
        float4 x = a[k];
        x.x *= inv0; x.y *= inv0; x.z *= inv0; x.w *= inv0;
        o0[lane + 32 * k] = x;
    }
#pragma unroll
    for (int k = 0; k < 4; k++) {
        float4 x = c[k];
        x.x *= inv1; x.y *= inv1; x.z *= inv1; x.w *= inv1;
        o1[lane + 32 * k] = x;
    }
}

// ---------------- kernel 7: binomial loss -> tail of output -------------------
__global__ void loss_kernel(float* __restrict__ out, long long out_size) {
    __shared__ double sh[BB];
    __shared__ float sh_loss;
    int tid = threadIdx.x;
    if (tid < BB) {
        double k = (double)g_count[tid];
        double n = (double)SS;
        double lp = lgamma(n + 1.0) - lgamma(k + 1.0) - lgamma(n - k + 1.0)
                  + k * log(0.2) + (n - k) * log1p(-0.2);
        sh[tid] = lp;
    }
    __syncthreads();
    if (tid == 0) {
        double m = 0.0;
        for (int b = 0; b < BB; b++) m += sh[b];
        m /= (double)BB;
        sh_loss = (float)(-m / (double)SS);
    }
    __syncthreads();
    long long start = (long long)BB * SS * DD;
    for (long long i = start + tid; i < out_size; i += blockDim.x) out[i] = sh_loss;
}

// ---------------- launch ------------------------------------------------------
extern "C" void kernel_launch(void* const* d_in, const int* in_sizes, int n_in,
                              void* d_out, int out_size) {
    const float* hidden = (const float*)d_in[0];
    const float* Wq     = (const float*)d_in[1];
    const float* Wk     = (const float*)d_in[2];
    const float* noise  = (const float*)d_in[3];
    float* out = (float*)d_out;

    zero_hs_kernel<<<(BB * DD + 511) / 512, 512>>>();
    invnorm_kernel<<<1024, 256>>>(hidden);
    hs_kernel<<<1024, 256>>>(hidden);
    matvec_kernel<<<BB, DD>>>(Wq, Wk);
    scores_kernel<<<1024, 256>>>(hidden, noise);
    scan_kernel<<<BB, 1024>>>();
    writeout_kernel<<<(BB * SS) / 16, 256>>>(hidden, out);
    loss_kernel<<<1, 256>>>(out, (long long)out_size);
}

// round 6
// speedup vs baseline: 2.0935x; 1.9002x over previous
#include <cuda_runtime.h>
#include <math.h>

#define BB 16
#define SS 8192
#define DD 512
#define SCALE_F 0.125
#define PAD 33   // smem row pad (floats): conflict-free scalar reads

// ---------------- scratch (__device__ globals; no allocations allowed) --------
__device__ double        g_hs[BB * DD];        // sum of normalized tokens per batch (fp64)
__device__ double        g_t[BB * DD];         // t = Wk @ hs (fp64)
__device__ double        g_vpart[BB * 8 * DD]; // stage2 partials (fp64)
__device__ float         g_v[BB * DD];         // v[b] = Wq^T (Wk hs[b])
__device__ float         g_invnorm[BB * SS];   // 1/max(||hidden_row||, 1e-12)
__device__ unsigned char g_hard[BB * SS];      // boundary bits
__device__ int           g_keptidx[BB * SS];   // compacted kept indices per batch
__device__ int           g_count[BB];          // kept counts

// ---------------- kernel 0: zero hs ------------------------------------------
__global__ void zero_hs_kernel() {
    int i = blockIdx.x * blockDim.x + threadIdx.x;
    if (i < BB * DD) g_hs[i] = 0.0;
}

// ---------------- kernel 1: invnorm (pure stream + warp-local smem reduce) ----
__global__ void __launch_bounds__(256, 4) invnorm_kernel(const float* __restrict__ hidden) {
    __shared__ float part[128 * PAD];
    int warp = threadIdx.x >> 5;
    int lane = threadIdx.x & 31;
    int batch = blockIdx.x >> 6;
    int tok0  = ((blockIdx.x & 63) * 8 + warp) * 16;

    const float4* base = (const float4*)(hidden + (size_t)batch * SS * DD);
#pragma unroll
    for (int t = 0; t < 16; t += 2) {
#pragma unroll
        for (int i = 0; i < 2; i++) {
            const float4* row = base + (size_t)(tok0 + t + i) * (DD / 4);
            float4 x0 = row[lane];
            float4 x1 = row[lane + 32];
            float4 x2 = row[lane + 64];
            float4 x3 = row[lane + 96];
            float s0 = 0.f, s1 = 0.f, s2 = 0.f, s3 = 0.f;
            s0 = fmaf(x0.x, x0.x, s0); s1 = fmaf(x0.y, x0.y, s1);
            s2 = fmaf(x0.z, x0.z, s2); s3 = fmaf(x0.w, x0.w, s3);
            s0 = fmaf(x1.x, x1.x, s0); s1 = fmaf(x1.y, x1.y, s1);
            s2 = fmaf(x1.z, x1.z, s2); s3 = fmaf(x1.w, x1.w, s3);
            s0 = fmaf(x2.x, x2.x, s0); s1 = fmaf(x2.y, x2.y, s1);
            s2 = fmaf(x2.z, x2.z, s2); s3 = fmaf(x2.w, x2.w, s3);
            s0 = fmaf(x3.x, x3.x, s0); s1 = fmaf(x3.y, x3.y, s1);
            s2 = fmaf(x3.z, x3.z, s2); s3 = fmaf(x3.w, x3.w, s3);
            part[(warp * 16 + t + i) * PAD + lane] = (s0 + s1) + (s2 + s3);
        }
    }
    __syncwarp();
    if (lane < 16) {
        int r = warp * 16 + lane;
        const float* p = &part[r * PAD];
        float q[32];
#pragma unroll
        for (int j = 0; j < 32; j++) q[j] = p[j];
#pragma unroll
        for (int w = 16; w > 0; w >>= 1)
#pragma unroll
            for (int j = 0; j < 32; j++) if (j < w) q[j] = q[j] + q[j + w];
        g_invnorm[batch * SS + tok0 + lane] = 1.0f / fmaxf(sqrtf(q[0]), 1e-12f);
    }
}

// ---------------- kernel 2: hs accumulation (pure stream) ---------------------
__global__ void __launch_bounds__(256, 4) hs_kernel(const float* __restrict__ hidden) {
    __shared__ float sh_warp[8 * DD];
    int warp = threadIdx.x >> 5;
    int lane = threadIdx.x & 31;
    int batch = blockIdx.x >> 6;
    int tok0  = ((blockIdx.x & 63) * 8 + warp) * 16;

    float accf[16];
#pragma unroll
    for (int k = 0; k < 16; k++) accf[k] = 0.0f;

    const float4* base = (const float4*)(hidden + (size_t)batch * SS * DD);
    const float* invp = g_invnorm + batch * SS + tok0;
#pragma unroll
    for (int t = 0; t < 16; t += 2) {
        float inv0 = invp[t];
        float inv1 = invp[t + 1];
        float4 x[2][4];
#pragma unroll
        for (int i = 0; i < 2; i++) {
            const float4* row = base + (size_t)(tok0 + t + i) * (DD / 4);
#pragma unroll
            for (int k = 0; k < 4; k++) x[i][k] = row[lane + 32 * k];
        }
#pragma unroll
        for (int k = 0; k < 4; k++) {
            accf[4 * k + 0] = fmaf(x[0][k].x, inv0, accf[4 * k + 0]);
            accf[4 * k + 1] = fmaf(x[0][k].y, inv0, accf[4 * k + 1]);
            accf[4 * k + 2] = fmaf(x[0][k].z, inv0, accf[4 * k + 2]);
            accf[4 * k + 3] = fmaf(x[0][k].w, inv0, accf[4 * k + 3]);
            accf[4 * k + 0] = fmaf(x[1][k].x, inv1, accf[4 * k + 0]);
            accf[4 * k + 1] = fmaf(x[1][k].y, inv1, accf[4 * k + 1]);
            accf[4 * k + 2] = fmaf(x[1][k].z, inv1, accf[4 * k + 2]);
            accf[4 * k + 3] = fmaf(x[1][k].w, inv1, accf[4 * k + 3]);
        }
    }
    float* my = sh_warp + warp * DD;
#pragma unroll
    for (int k = 0; k < 4; k++) {
        int c = 4 * (lane + 32 * k);
        my[c + 0] = accf[4 * k + 0];
        my[c + 1] = accf[4 * k + 1];
        my[c + 2] = accf[4 * k + 2];
        my[c + 3] = accf[4 * k + 3];
    }
    __syncthreads();
    for (int c = threadIdx.x; c < DD; c += blockDim.x) {
        double s = 0.0;
#pragma unroll
        for (int w = 0; w < 8; w++) s += (double)sh_warp[w * DD + c];
        atomicAdd(&g_hs[batch * DD + c], s);
    }
}

// ---------------- kernel 3a: t[b,d] = Wk[d,:] . hs[b]  (parallel, fp64) -------
// grid = BB*32 = 512 blocks, 256 thr (8 warps), warp = 2 rows, 16 rows/block.
__global__ void __launch_bounds__(256, 4) matvec1_kernel(const float* __restrict__ Wk) {
    __shared__ double sh_hs[DD];
    int b = blockIdx.x >> 5;                 // 32 blocks per batch
    int row0 = (blockIdx.x & 31) * 16;       // 16 rows per block
    for (int i = threadIdx.x; i < DD; i += blockDim.x) sh_hs[i] = g_hs[b * DD + i];
    __syncthreads();

    int warp = threadIdx.x >> 5, lane = threadIdx.x & 31;
    int r0 = row0 + warp * 2;

    // 2 rows in flight: 8 LDG.128
    float4 x[2][4];
#pragma unroll
    for (int i = 0; i < 2; i++) {
        const float4* wr = (const float4*)(Wk + (size_t)(r0 + i) * DD);
#pragma unroll
        for (int k = 0; k < 4; k++) x[i][k] = wr[lane + 32 * k];
    }
    double dot[2];
#pragma unroll
    for (int i = 0; i < 2; i++) {
        double a0 = 0.0, a1 = 0.0, a2 = 0.0, a3 = 0.0;
#pragma unroll
        for (int k = 0; k < 4; k++) {
            int c = 4 * (lane + 32 * k);
            a0 += (double)x[i][k].x * sh_hs[c + 0];
            a1 += (double)x[i][k].y * sh_hs[c + 1];
            a2 += (double)x[i][k].z * sh_hs[c + 2];
            a3 += (double)x[i][k].w * sh_hs[c + 3];
        }
        dot[i] = (a0 + a1) + (a2 + a3);
    }
#pragma unroll
    for (int o = 16; o > 0; o >>= 1) {
        dot[0] += __shfl_xor_sync(0xffffffffu, dot[0], o);
        dot[1] += __shfl_xor_sync(0xffffffffu, dot[1], o);
    }
    if (lane < 2) g_t[b * DD + r0 + lane] = (lane == 0) ? dot[0] : dot[1];
}

// ---------------- kernel 3b: vpart[b,chunk,e] = sum_{d in chunk} Wq[d,e]*t[b,d]
// grid = BB*8 = 128 blocks, 512 thr. Coalesced Wq columns, 4 fp64 chains.
__global__ void __launch_bounds__(512, 2) matvec2_kernel(const float* __restrict__ Wq) {
    __shared__ double sh_t[64];
    int b = blockIdx.x >> 3;
    int chunk = blockIdx.x & 7;
    int d0 = chunk * 64;
    if (threadIdx.x < 64) sh_t[threadIdx.x] = g_t[b * DD + d0 + threadIdx.x];
    __syncthreads();

    int e = threadIdx.x;
    const float* wp = Wq + (size_t)d0 * DD + e;
    double a0 = 0.0, a1 = 0.0, a2 = 0.0, a3 = 0.0;
#pragma unroll 4
    for (int d = 0; d < 64; d += 4) {
        a0 += (double)wp[(size_t)(d + 0) * DD] * sh_t[d + 0];
        a1 += (double)wp[(size_t)(d + 1) * DD] * sh_t[d + 1];
        a2 += (double)wp[(size_t)(d + 2) * DD] * sh_t[d + 2];
        a3 += (double)wp[(size_t)(d + 3) * DD] * sh_t[d + 3];
    }
    g_vpart[((size_t)b * 8 + chunk) * DD + e] = (a0 + a1) + (a2 + a3);
}

// ---------------- kernel 3c: combine partials -> g_v (fixed order) ------------
__global__ void matvec3_kernel() {
    int b = blockIdx.x;
    int e = threadIdx.x;
    double s = 0.0;
#pragma unroll
    for (int c = 0; c < 8; c++) s += g_vpart[((size_t)b * 8 + c) * DD + e];
    g_v[b * DD + e] = (float)s;
}

// ---------------- kernel 4: scores + hard bits (stream + warp-local reduce) ---
__global__ void __launch_bounds__(256, 4) scores_kernel(const float* __restrict__ hidden,
                                                        const float* __restrict__ noise) {
    __shared__ float part[128 * PAD];
    __shared__ float sh_v[DD];
    int warp = threadIdx.x >> 5;
    int lane = threadIdx.x & 31;
    int batch = blockIdx.x >> 6;
    int tok0  = ((blockIdx.x & 63) * 8 + warp) * 16;

    for (int i = threadIdx.x; i < DD; i += blockDim.x) sh_v[i] = g_v[batch * DD + i];
    __syncthreads();

    const float4* vv = (const float4*)sh_v;
    float4 w0 = vv[lane], w1 = vv[lane + 32], w2 = vv[lane + 64], w3 = vv[lane + 96];

    const float4* base = (const float4*)(hidden + (size_t)batch * SS * DD);
#pragma unroll
    for (int t = 0; t < 16; t += 2) {
#pragma unroll
        for (int i = 0; i < 2; i++) {
            const float4* row = base + (size_t)(tok0 + t + i) * (DD / 4);
            float4 x0 = row[lane];
            float4 x1 = row[lane + 32];
            float4 x2 = row[lane + 64];
            float4 x3 = row[lane + 96];
            float s0 = 0.f, s1 = 0.f, s2 = 0.f, s3 = 0.f;
            s0 = fmaf(x0.x, w0.x, s0); s1 = fmaf(x0.y, w0.y, s1);
            s2 = fmaf(x0.z, w0.z, s2); s3 = fmaf(x0.w, w0.w, s3);
            s0 = fmaf(x1.x, w1.x, s0); s1 = fmaf(x1.y, w1.y, s1);
            s2 = fmaf(x1.z, w1.z, s2); s3 = fmaf(x1.w, w1.w, s3);
            s0 = fmaf(x2.x, w2.x, s0); s1 = fmaf(x2.y, w2.y, s1);
            s2 = fmaf(x2.z, w2.z, s2); s3 = fmaf(x2.w, w2.w, s3);
            s0 = fmaf(x3.x, w3.x, s0); s1 = fmaf(x3.y, w3.y, s1);
            s2 = fmaf(x3.z, w3.z, s2); s3 = fmaf(x3.w, w3.w, s3);
            part[(warp * 16 + t + i) * PAD + lane] = (s0 + s1) + (s2 + s3);
        }
    }
    __syncwarp();
    if (lane < 16) {
        int r = warp * 16 + lane;
        const float* p = &part[r * PAD];
        double q[16];
#pragma unroll
        for (int j = 0; j < 16; j++) q[j] = (double)p[j] + (double)p[j + 16];
#pragma unroll
        for (int w = 8; w > 0; w >>= 1)
#pragma unroll
            for (int j = 0; j < 16; j++) if (j < w) q[j] = q[j] + q[j + w];
        int g = batch * SS + tok0 + lane;
        double score = SCALE_F * (double)g_invnorm[g] * q[0];
        float nz = noise[g];
        double logistic = (double)logf(nz) - (double)log1pf(-nz);
        g_hard[g] = (score + logistic > 0.0) ? 1 : 0;
    }
}

// ---------------- kernel 5: per-batch stable compaction scan ------------------
__global__ void scan_kernel() {
    int b = blockIdx.x;
    int tid = threadIdx.x;
    const int TPT = SS / 1024;  // 8
    int base = b * SS + tid * TPT;

    int loc[TPT];
    int cnt = 0;
#pragma unroll
    for (int i = 0; i < TPT; i++) { loc[i] = g_hard[base + i]; cnt += loc[i]; }

    int lane = tid & 31, warp = tid >> 5;
    int v = cnt;
#pragma unroll
    for (int o = 1; o < 32; o <<= 1) {
        int n = __shfl_up_sync(0xffffffffu, v, o);
        if (lane >= o) v += n;
    }
    __shared__ int wsum[32];
    if (lane == 31) wsum[warp] = v;
    __syncthreads();
    if (warp == 0) {
        int w = wsum[lane];
#pragma unroll
        for (int o = 1; o < 32; o <<= 1) {
            int n = __shfl_up_sync(0xffffffffu, w, o);
            if (lane >= o) w += n;
        }
        wsum[lane] = w;
    }
    __syncthreads();
    int excl = (v - cnt) + (warp > 0 ? wsum[warp - 1] : 0);

    int pos = excl;
#pragma unroll
    for (int i = 0; i < TPT; i++)
        if (loc[i]) g_keptidx[b * SS + (pos++)] = tid * TPT + i;
    if (tid == 1023) g_count[b] = excl + cnt;
}

// ---------------- kernel 6: write pooled (gather kept rows, zero the rest) ----
__global__ void __launch_bounds__(256, 4) writeout_kernel(const float* __restrict__ hidden,
                                                          float* __restrict__ out) {
    int wg = blockIdx.x * (blockDim.x >> 5) + (threadIdx.x >> 5);
    int lane = threadIdx.x & 31;
    int b = wg >> 12;          // 4096 warps per batch (2 rows each)
    int i0 = (wg & 4095) * 2;
    int cnt = g_count[b];

    bool v0 = i0 < cnt, v1 = (i0 + 1) < cnt;
    int s0 = v0 ? g_keptidx[b * SS + i0] : 0;
    int s1 = v1 ? g_keptidx[b * SS + i0 + 1] : 0;
    float inv0 = v0 ? g_invnorm[b * SS + s0] : 0.f;
    float inv1 = v1 ? g_invnorm[b * SS + s1] : 0.f;

    const float4* r0 = (const float4*)hidden + ((size_t)b * SS + s0) * (DD / 4);
    const float4* r1 = (const float4*)hidden + ((size_t)b * SS + s1) * (DD / 4);
    float4 a[4], c[4];
    float4 z = make_float4(0.f, 0.f, 0.f, 0.f);
#pragma unroll
    for (int k = 0; k < 4; k++) a[k] = v0 ? r0[lane + 32 * k] : z;
#pragma unroll
    for (int k = 0; k < 4; k++) c[k] = v1 ? r1[lane + 32 * k] : z;

    float4* o0 = (float4*)out + ((size_t)b * SS + i0) * (DD / 4);
    float4* o1 = o0 + (DD / 4);
#pragma unroll
    for (int k = 0; k < 4; k++) {
        float4 x = a[k];
        x.x *= inv0; x.y *= inv0; x.z *= inv0; x.w *= inv0;
        o0[lane + 32 * k] = x;
    }
#pragma unroll
    for (int k = 0; k < 4; k++) {
        float4 x = c[k];
        x.x *= inv1; x.y *= inv1; x.z *= inv1; x.w *= inv1;
        o1[lane + 32 * k] = x;
    }
}

// ---------------- kernel 7: binomial loss -> tail of output -------------------
__global__ void loss_kernel(float* __restrict__ out, long long out_size) {
    __shared__ double sh[BB];
    __shared__ float sh_loss;
    int tid = threadIdx.x;
    if (tid < BB) {
        double k = (double)g_count[tid];
        double n = (double)SS;
        double lp = lgamma(n + 1.0) - lgamma(k + 1.0) - lgamma(n - k + 1.0)
                  + k * log(0.2) + (n - k) * log1p(-0.2);
        sh[tid] = lp;
    }
    __syncthreads();
    if (tid == 0) {
        double m = 0.0;
        for (int b = 0; b < BB; b++) m += sh[b];
        m /= (double)BB;
        sh_loss = (float)(-m / (double)SS);
    }
    __syncthreads();
    long long start = (long long)BB * SS * DD;
    for (long long i = start + tid; i < out_size; i += blockDim.x) out[i] = sh_loss;
}

// ---------------- launch ------------------------------------------------------
extern "C" void kernel_launch(void* const* d_in, const int* in_sizes, int n_in,
                              void* d_out, int out_size) {
    const float* hidden = (const float*)d_in[0];
    const float* Wq     = (const float*)d_in[1];
    const float* Wk     = (const float*)d_in[2];
    const float* noise  = (const float*)d_in[3];
    float* out = (float*)d_out;

    zero_hs_kernel<<<(BB * DD + 511) / 512, 512>>>();
    invnorm_kernel<<<1024, 256>>>(hidden);
    hs_kernel<<<1024, 256>>>(hidden);
    matvec1_kernel<<<BB * 32, 256>>>(Wk);
    matvec2_kernel<<<BB * 8, 512>>>(Wq);
    matvec3_kernel<<<BB, DD>>>();
    scores_kernel<<<1024, 256>>>(hidden, noise);
    scan_kernel<<<BB, 1024>>>();
    writeout_kernel<<<(BB * SS) / 16, 256>>>(hidden, out);
    loss_kernel<<<1, 256>>>(out, (long long)out_size);
}